// round 16
// baseline (speedup 1.0000x reference)
#include <cuda_runtime.h>
#include <cmath>

#define S_LEN  1024
#define BATCHN 128
#define IDIM   256
#define HDIM   512
#define ODIM   64

typedef unsigned long long ull;

// ---------- f32x2 packed helpers ----------
__device__ __forceinline__ ull splat2(float x) {
    ull r; asm("mov.b64 %0, {%1, %1};" : "=l"(r) : "f"(x)); return r;
}
__device__ __forceinline__ ull ffma2(ull a, ull b, ull c) {
    ull d; asm("fma.rn.f32x2 %0, %1, %2, %3;" : "=l"(d) : "l"(a), "l"(b), "l"(c)); return d;
}
__device__ __forceinline__ ull add2(ull a, ull b) {
    ull d; asm("add.rn.f32x2 %0, %1, %2;" : "=l"(d) : "l"(a), "l"(b)); return d;
}
__device__ __forceinline__ float2 upk2(ull v) {
    float2 f; asm("mov.b64 {%0, %1}, %2;" : "=f"(f.x), "=f"(f.y) : "l"(v)); return f;
}
__device__ __forceinline__ unsigned s2u32(const void* p) {
    unsigned a;
    asm("{ .reg .u64 t; cvta.to.shared.u64 t, %1; cvt.u32.u64 %0, t; }" : "=r"(a) : "l"(p));
    return a;
}
__device__ __forceinline__ unsigned mapa_rank(unsigned a, unsigned r) {
    unsigned d; asm("mapa.shared::cluster.u32 %0, %1, %2;" : "=r"(d) : "r"(a), "r"(r));
    return d;
}
__device__ __forceinline__ void bulk_s2c(unsigned dst, unsigned src, unsigned bytes,
                                         unsigned mbar) {
    asm volatile(
        "cp.async.bulk.shared::cluster.shared::cta.mbarrier::complete_tx::bytes "
        "[%0], [%1], %2, [%3];"
        :: "r"(dst), "r"(src), "r"(bytes), "r"(mbar) : "memory");
}
__device__ __forceinline__ void mbar_init(unsigned mbar, unsigned cnt) {
    asm volatile("mbarrier.init.shared.b64 [%0], %1;" :: "r"(mbar), "r"(cnt) : "memory");
}
__device__ __forceinline__ void mbar_expect_tx(unsigned mbar, unsigned bytes) {
    asm volatile("mbarrier.arrive.expect_tx.shared.b64 _, [%0], %1;"
                 :: "r"(mbar), "r"(bytes) : "memory");
}
__device__ __forceinline__ void mbar_wait_parity(unsigned mbar, unsigned parity) {
    asm volatile(
        "{\n\t"
        ".reg .pred P;\n"
        "LW_%=:\n\t"
        "mbarrier.try_wait.parity.acquire.cta.shared::cta.b64 P, [%0], %1, 0x989680;\n\t"
        "@P bra LD_%=;\n\t"
        "bra LW_%=;\n"
        "LD_%=:\n\t"
        "}"
        :: "r"(mbar), "r"(parity) : "memory");
}
__device__ __forceinline__ unsigned elect1() {
    unsigned p;
    asm volatile("{\n\t.reg .pred p;\n\telect.sync _|p, 0xFFFFFFFF;\n\t"
                 "selp.b32 %0, 1, 0, p;\n\t}" : "=r"(p));
    return p;
}
__device__ __forceinline__ void bar_sync_n(unsigned id, unsigned n) {
    asm volatile("bar.sync %0, %1;" :: "r"(id), "r"(n) : "memory");
}
__device__ __forceinline__ void bar_arrive_n(unsigned id, unsigned n) {
    asm volatile("bar.arrive %0, %1;" :: "r"(id), "r"(n) : "memory");
}

// ---------- scratch (device globals: allocation-free rule) ----------
__device__ float g_xp[(size_t)BATCHN * S_LEN * HDIM];  // X@W_ih + b_hh, [b][s][h]
__device__ float g_h [(size_t)BATCHN * S_LEN * HDIM];  // hidden states,  [b][s][h]

// ============================================================================
// Kernel A: g_xp[M,512] = X[M,256] @ W_ih[256,512] + b_hh, M = 131072
// ============================================================================
__global__ void __launch_bounds__(256, 2) xproj_kernel(
    const float* __restrict__ X, const float* __restrict__ Wih,
    const float* __restrict__ bhh)
{
    __shared__ float As[128][17];
    __shared__ float Bs[16][128];
    const int tid = threadIdx.x;
    const int m0 = blockIdx.x * 128;
    const int n0 = blockIdx.y * 128;
    const int tx = tid & 15, ty = tid >> 4;

    ull acc[8][4];
#pragma unroll
    for (int i = 0; i < 8; i++)
#pragma unroll
        for (int j = 0; j < 4; j++) acc[i][j] = 0ull;

    for (int k0 = 0; k0 < IDIM; k0 += 16) {
#pragma unroll
        for (int i = 0; i < 2; i++) {
            int f4  = tid + i * 256;
            int row = f4 >> 2;
            int c4  = (f4 & 3) << 2;
            float4 v = *(const float4*)(X + (size_t)(m0 + row) * IDIM + k0 + c4);
            As[row][c4 + 0] = v.x; As[row][c4 + 1] = v.y;
            As[row][c4 + 2] = v.z; As[row][c4 + 3] = v.w;
        }
#pragma unroll
        for (int i = 0; i < 2; i++) {
            int f4  = tid + i * 256;
            int row = f4 >> 5;
            int c4  = (f4 & 31) << 2;
            *(float4*)&Bs[row][c4] =
                *(const float4*)(Wih + (size_t)(k0 + row) * HDIM + n0 + c4);
        }
        __syncthreads();
#pragma unroll
        for (int k = 0; k < 16; k++) {
            ulonglong2 bv0 = *(const ulonglong2*)&Bs[k][tx * 4];
            ulonglong2 bv1 = *(const ulonglong2*)&Bs[k][64 + tx * 4];
#pragma unroll
            for (int i = 0; i < 8; i++) {
                ull a2 = splat2(As[ty * 8 + i][k]);
                acc[i][0] = ffma2(a2, bv0.x, acc[i][0]);
                acc[i][1] = ffma2(a2, bv0.y, acc[i][1]);
                acc[i][2] = ffma2(a2, bv1.x, acc[i][2]);
                acc[i][3] = ffma2(a2, bv1.y, acc[i][3]);
            }
        }
        __syncthreads();
    }

#pragma unroll
    for (int i = 0; i < 8; i++) {
        float* dst = g_xp + (size_t)(m0 + ty * 8 + i) * HDIM + n0;
#pragma unroll
        for (int j = 0; j < 4; j++) {
            int n = (j < 2) ? (tx * 4 + j * 2) : (64 + tx * 4 + (j - 2) * 2);
            float2 v = upk2(acc[i][j]);
            v.x += bhh[n0 + n];
            v.y += bhh[n0 + n + 1];
            *(float2*)(dst + n) = v;
        }
    }
}

// empty launch to shift ncu's fixed profiled-launch slot onto rnn_kernel
__global__ void dummy_kernel() {}

// ============================================================================
// Kernel B: serial recurrence, BATCH-SPLIT software pipeline.
// 16 clusters x 8 CTAs; rank r owns W_hh cols [64r,64r+64) as ull col-pairs.
// 512 threads. Two independent 4-batch recurrences (A = batches 0-3,
// B = 4-7) interleaved: group A's DSMEM flight overlaps group B's phase1
// and vice versa -> flight leaves the loop-carried critical path.
//
// hx layout: [grp][slot][src][kLocal64][bi4] floats.
//   float strides: grp 4096, slot 2048, src 256.
//   BYTE  strides: grp 16384, slot 8192, src 1024.   (push uses BYTES!)
// ============================================================================
#define NT 512
// float offsets: Wp 32768 | prt[2 grp] 8192 | hx[2][2][8][256] 8192
#define F_PRT 32768
#define F_HX  40960
#define HX_BYTE 163840u
#define MB_BYTE 196608u               // 32 mbars: (grp*16 + src*2 + slot)*8
#define SMEMB_BYTES (196608 + 256)
#define BSTRIDE ((size_t)S_LEN * HDIM)
#define BLK_BYTES 1024u               // one (grp, src) block: 64k x 4b floats
#define SLOT_BYTES 8192u              // slot stride in BYTES (2048 floats)

__global__ void __launch_bounds__(NT, 1) __cluster_dims__(8, 1, 1)
rnn_kernel(const float* __restrict__ Whh)
{
    extern __shared__ float sm[];
    ull* Wp   = (ull*)sm;              // [k][jp], k stride 32 ull
    ull* prt  = (ull*)(sm + F_PRT);    // [grp][w16][b4][cp32]
    float* hx = sm + F_HX;             // [grp][slot][src][kLocal64][bi4]

    const int tid  = threadIdx.x;
    const int rank = blockIdx.x & 7;
    const int g    = blockIdx.x >> 3;
    const int c0   = rank * 64;
    const unsigned smb    = s2u32(sm);
    const unsigned mb_loc = smb + MB_BYTE;

    if (tid == 0) {
#pragma unroll
        for (int i = 0; i < 32; i++) {
            mbar_init(mb_loc + i * 8, 1);
            mbar_expect_tx(mb_loc + i * 8, BLK_BYTES);
        }
    }

    // Load W_hh slice once as column pairs (128KB)
    for (int i = tid; i < HDIM * 32; i += NT) {
        int k = i >> 5, jp = i & 31;
        *(float2*)(Wp + i) = *(const float2*)(Whh + (size_t)k * HDIM + c0 + 2 * jp);
    }
    // zero hx (h0 = 0): both groups, both slots
    for (int i = tid; i < 8192; i += NT) hx[i] = 0.f;
    __syncthreads();
    asm volatile("barrier.cluster.arrive.aligned;" ::: "memory");
    asm volatile("barrier.cluster.wait.aligned;"   ::: "memory");

    const int w  = tid >> 5, l = tid & 31;
    const int rg = l >> 4,  ls = l & 15;
    const int kbeg = w * 32;
    const int sw   = w >> 1;                    // source rank for this k-chunk
    const bool self_src = (sw == rank);

    // phase-1 pointers (shared by both groups; group adds grp*4096 floats)
    const ull*   wsp  = Wp + (size_t)kbeg * 32 + ls;         // [k*32], [k*32+16]
    const float* hxk  = hx + sw * 256 + (w & 1) * 128 + 2 * rg;  // + grp*4096 + slot*2048 + k*4
    ull*         pwb  = prt + w * 128;                       // + grp*2048

    // reducer mapping (warps 0-7): grp = w>>2, b = w&3, lane l = col-pair
    const ull* pq = prt + (w >> 2) * 2048 + (w & 3) * 32 + l;
    const float* xpp = g_xp + ((size_t)(g * 8 + w)) * BSTRIDE + c0 + 2 * l;
    float*       ghw = g_h  + ((size_t)(g * 8 + w)) * BSTRIDE + c0 + 2 * l;
    // own-block STS: hx[grp][slot][rank][2l(+1)][b]
    float* hxo = hx + (w >> 2) * 4096 + rank * 256 + 8 * l + (w & 3);  // + slot*2048

    // push targets (warp 0 -> group A, warp 4 -> group B), lane < 7, rotated
    unsigned push_hx = 0, push_mb = 0, push_src = 0;
    if ((w == 0 || w == 4) && l < 7) {
        const unsigned pg  = (w == 4) ? 1u : 0u;
        const unsigned hx0 = smb + HX_BYTE + pg * 16384u + (unsigned)rank * BLK_BYTES;
        const unsigned mb0 = mb_loc + (pg * 16u + (unsigned)rank * 2u) * 8u;
        const unsigned r   = (unsigned)((rank + 1 + l) & 7);
        push_hx  = mapa_rank(hx0, r);
        push_mb  = mapa_rank(mb0, r);
        push_src = hx0;
    }
    const unsigned mbA = mb_loc + (unsigned)(sw * 2) * 8u;          // + slot*8
    const unsigned mbB = mb_loc + (16u + (unsigned)(sw * 2)) * 8u;  // + slot*8
    const bool rearm_warp = ((w & 1) == 0);

    for (int t = 0; t < S_LEN; t++) {
        const int wb = t & 1, rb = wb ^ 1;
        const unsigned par  = (unsigned)(((t - 1) >> 1) & 1);
        const bool     last = (t == S_LEN - 1);

        // xp prefetch (reducers)
        ull xv = 0;
        if (w < 8) xv = *(const ull*)(xpp + (size_t)t * HDIM);

        // ================= group A =================
        if (t > 0 && !self_src) {
            mbar_wait_parity(mbA + (unsigned)(rb * 8), par);
            if (rearm_warp && elect1()) mbar_expect_tx(mbA + (unsigned)(rb * 8), BLK_BYTES);
        }
        {
            const float* hk = hxk + rb * 2048;           // group A, read slot (floats)
            ull a00 = 0, a01 = 0, a10 = 0, a11 = 0;
#pragma unroll 4
            for (int k = 0; k < 32; k++) {
                ull w0 = wsp[k * 32];
                ull w1 = wsp[k * 32 + 16];
                float2 hv = *(const float2*)(hk + k * 4);
                ull h0 = splat2(hv.x), h1 = splat2(hv.y);
                a00 = ffma2(w0, h0, a00);
                a01 = ffma2(w0, h1, a01);
                a10 = ffma2(w1, h0, a10);
                a11 = ffma2(w1, h1, a11);
            }
            ull* pw = pwb;                               // group A partials
            pw[(2 * rg) * 32 + ls]          = a00;
            pw[(2 * rg + 1) * 32 + ls]      = a01;
            pw[(2 * rg) * 32 + ls + 16]     = a10;
            pw[(2 * rg + 1) * 32 + ls + 16] = a11;
        }
        if (w < 4) {
            bar_sync_n(1u, 512u);                        // all prt_A in
            ull q0 = add2(pq[0 * 128],  pq[1 * 128]);
            ull q1 = add2(pq[2 * 128],  pq[3 * 128]);
            ull q2 = add2(pq[4 * 128],  pq[5 * 128]);
            ull q3 = add2(pq[6 * 128],  pq[7 * 128]);
            ull q4 = add2(pq[8 * 128],  pq[9 * 128]);
            ull q5 = add2(pq[10 * 128], pq[11 * 128]);
            ull q6 = add2(pq[12 * 128], pq[13 * 128]);
            ull q7 = add2(pq[14 * 128], pq[15 * 128]);
            q0 = add2(q0, q1); q2 = add2(q2, q3);
            q4 = add2(q4, q5); q6 = add2(q6, q7);
            q0 = add2(q0, q2); q4 = add2(q4, q6);
            ull s = add2(xv, add2(q0, q4));
            float2 sv = upk2(s);
            float h0 = tanhf(sv.x);
            float h1 = tanhf(sv.y);
            *(float2*)(ghw + (size_t)t * HDIM) = make_float2(h0, h1);
            if (!last) {
                hxo[wb * 2048]     = h0;                 // kLocal = 2l   (floats)
                hxo[wb * 2048 + 4] = h1;                 // kLocal = 2l+1
                bar_sync_n(3u, 128u);                    // reducersA STS done
                if (w == 0 && l < 7) {
                    asm volatile("fence.proxy.async.shared::cta;" ::: "memory");
                    bulk_s2c(push_hx + (unsigned)wb * SLOT_BYTES,
                             push_src + (unsigned)wb * SLOT_BYTES,
                             BLK_BYTES,
                             push_mb + (unsigned)(wb * 8));
                }
            }
        } else {
            bar_arrive_n(1u, 512u);
        }

        // ================= group B =================
        if (t > 0 && !self_src) {
            mbar_wait_parity(mbB + (unsigned)(rb * 8), par);
            if (rearm_warp && elect1()) mbar_expect_tx(mbB + (unsigned)(rb * 8), BLK_BYTES);
        }
        {
            const float* hk = hxk + 4096 + rb * 2048;    // group B, read slot (floats)
            ull a00 = 0, a01 = 0, a10 = 0, a11 = 0;
#pragma unroll 4
            for (int k = 0; k < 32; k++) {
                ull w0 = wsp[k * 32];
                ull w1 = wsp[k * 32 + 16];
                float2 hv = *(const float2*)(hk + k * 4);
                ull h0 = splat2(hv.x), h1 = splat2(hv.y);
                a00 = ffma2(w0, h0, a00);
                a01 = ffma2(w0, h1, a01);
                a10 = ffma2(w1, h0, a10);
                a11 = ffma2(w1, h1, a11);
            }
            ull* pw = pwb + 2048;                        // group B partials
            pw[(2 * rg) * 32 + ls]          = a00;
            pw[(2 * rg + 1) * 32 + ls]      = a01;
            pw[(2 * rg) * 32 + ls + 16]     = a10;
            pw[(2 * rg + 1) * 32 + ls + 16] = a11;
        }
        if (w >= 4 && w < 8) {
            bar_sync_n(5u, 512u);                        // all prt_B in
            ull q0 = add2(pq[0 * 128],  pq[1 * 128]);
            ull q1 = add2(pq[2 * 128],  pq[3 * 128]);
            ull q2 = add2(pq[4 * 128],  pq[5 * 128]);
            ull q3 = add2(pq[6 * 128],  pq[7 * 128]);
            ull q4 = add2(pq[8 * 128],  pq[9 * 128]);
            ull q5 = add2(pq[10 * 128], pq[11 * 128]);
            ull q6 = add2(pq[12 * 128], pq[13 * 128]);
            ull q7 = add2(pq[14 * 128], pq[15 * 128]);
            q0 = add2(q0, q1); q2 = add2(q2, q3);
            q4 = add2(q4, q5); q6 = add2(q6, q7);
            q0 = add2(q0, q2); q4 = add2(q4, q6);
            ull s = add2(xv, add2(q0, q4));
            float2 sv = upk2(s);
            float h0 = tanhf(sv.x);
            float h1 = tanhf(sv.y);
            *(float2*)(ghw + (size_t)t * HDIM) = make_float2(h0, h1);
            if (!last) {
                hxo[wb * 2048]     = h0;
                hxo[wb * 2048 + 4] = h1;
                bar_sync_n(4u, 128u);                    // reducersB STS done
                if (w == 4 && l < 7) {
                    asm volatile("fence.proxy.async.shared::cta;" ::: "memory");
                    bulk_s2c(push_hx + (unsigned)wb * SLOT_BYTES,
                             push_src + (unsigned)wb * SLOT_BYTES,
                             BLK_BYTES,
                             push_mb + (unsigned)(wb * 8));
                }
            }
        } else {
            bar_arrive_n(5u, 512u);
        }

        if (!last) bar_sync_n(2u, 512u);   // step end: prt free + self-src STS visible
    }
}

// ============================================================================
// Kernel C: out[M,64] = g_h[M,512] @ W_ho[512,64] + b_ho, M = 131072
// ============================================================================
__global__ void __launch_bounds__(256) out_kernel(
    const float* __restrict__ Who, const float* __restrict__ bho,
    float* __restrict__ out)
{
    __shared__ float As[128][17];
    __shared__ float Bs[16][64];
    const int tid = threadIdx.x;
    const int m0 = blockIdx.x * 128;
    const int tx = tid & 15, ty = tid >> 4;

    ull acc[8][2];
#pragma unroll
    for (int i = 0; i < 8; i++) { acc[i][0] = 0ull; acc[i][1] = 0ull; }

    for (int k0 = 0; k0 < HDIM; k0 += 16) {
#pragma unroll
        for (int i = 0; i < 2; i++) {
            int f4  = tid + i * 256;
            int row = f4 >> 2;
            int c4  = (f4 & 3) << 2;
            float4 v = *(const float4*)(g_h + (size_t)(m0 + row) * HDIM + k0 + c4);
            As[row][c4 + 0] = v.x; As[row][c4 + 1] = v.y;
            As[row][c4 + 2] = v.z; As[row][c4 + 3] = v.w;
        }
        {
            int row = tid >> 4;
            int c4  = (tid & 15) << 2;
            *(float4*)&Bs[row][c4] =
                *(const float4*)(Who + (size_t)(k0 + row) * ODIM + c4);
        }
        __syncthreads();
#pragma unroll
        for (int k = 0; k < 16; k++) {
            ulonglong2 bv = *(const ulonglong2*)&Bs[k][tx * 4];
#pragma unroll
            for (int i = 0; i < 8; i++) {
                ull a2 = splat2(As[ty * 8 + i][k]);
                acc[i][0] = ffma2(a2, bv.x, acc[i][0]);
                acc[i][1] = ffma2(a2, bv.y, acc[i][1]);
            }
        }
        __syncthreads();
    }

    float bb0 = bho[tx * 4 + 0], bb1 = bho[tx * 4 + 1];
    float bb2 = bho[tx * 4 + 2], bb3 = bho[tx * 4 + 3];
#pragma unroll
    for (int i = 0; i < 8; i++) {
        float2 v0 = upk2(acc[i][0]); v0.x += bb0; v0.y += bb1;
        float2 v1 = upk2(acc[i][1]); v1.x += bb2; v1.y += bb3;
        float* dst = out + (size_t)(m0 + ty * 8 + i) * ODIM + tx * 4;
        *(float2*)(dst + 0) = v0;
        *(float2*)(dst + 2) = v1;
    }
}

// ============================================================================
extern "C" void kernel_launch(void* const* d_in, const int* in_sizes, int n_in,
                              void* d_out, int out_size)
{
    const float* X   = (const float*)d_in[0];   // [128,1024,256]
    const float* Whh = (const float*)d_in[1];   // [512,512]
    const float* Wih = (const float*)d_in[2];   // [256,512]
    const float* bhh = (const float*)d_in[3];   // [512]
    const float* Who = (const float*)d_in[4];   // [512,64]
    const float* bho = (const float*)d_in[5];   // [64]
    float* out = (float*)d_out;                 // [128,1024,64]

    cudaFuncSetAttribute(rnn_kernel,
                         cudaFuncAttributeMaxDynamicSharedMemorySize,
                         SMEMB_BYTES);

    xproj_kernel<<<dim3(1024, 4, 1), 256>>>(X, Wih, bhh);
    dummy_kernel<<<1, 32>>>();
    dummy_kernel<<<1, 32>>>();
    rnn_kernel<<<128, NT, SMEMB_BYTES>>>(Whh);
    out_kernel<<<1024, 256>>>(Who, bho, out);
}

// round 17
// speedup vs baseline: 1.0590x; 1.0590x over previous
#include <cuda_runtime.h>
#include <cmath>

#define S_LEN  1024
#define BATCHN 128
#define IDIM   256
#define HDIM   512
#define ODIM   64

typedef unsigned long long ull;

// ---------- f32x2 packed helpers ----------
__device__ __forceinline__ ull splat2(float x) {
    ull r; asm("mov.b64 %0, {%1, %1};" : "=l"(r) : "f"(x)); return r;
}
__device__ __forceinline__ ull ffma2(ull a, ull b, ull c) {
    ull d; asm("fma.rn.f32x2 %0, %1, %2, %3;" : "=l"(d) : "l"(a), "l"(b), "l"(c)); return d;
}
__device__ __forceinline__ ull add2(ull a, ull b) {
    ull d; asm("add.rn.f32x2 %0, %1, %2;" : "=l"(d) : "l"(a), "l"(b)); return d;
}
__device__ __forceinline__ float2 upk2(ull v) {
    float2 f; asm("mov.b64 {%0, %1}, %2;" : "=f"(f.x), "=f"(f.y) : "l"(v)); return f;
}
__device__ __forceinline__ unsigned s2u32(const void* p) {
    unsigned a;
    asm("{ .reg .u64 t; cvta.to.shared.u64 t, %1; cvt.u32.u64 %0, t; }" : "=r"(a) : "l"(p));
    return a;
}
__device__ __forceinline__ unsigned mapa_rank(unsigned a, unsigned r) {
    unsigned d; asm("mapa.shared::cluster.u32 %0, %1, %2;" : "=r"(d) : "r"(a), "r"(r));
    return d;
}
__device__ __forceinline__ void bulk_s2c(unsigned dst, unsigned src, unsigned bytes,
                                         unsigned mbar) {
    asm volatile(
        "cp.async.bulk.shared::cluster.shared::cta.mbarrier::complete_tx::bytes "
        "[%0], [%1], %2, [%3];"
        :: "r"(dst), "r"(src), "r"(bytes), "r"(mbar) : "memory");
}
__device__ __forceinline__ void mbar_init(unsigned mbar, unsigned cnt) {
    asm volatile("mbarrier.init.shared.b64 [%0], %1;" :: "r"(mbar), "r"(cnt) : "memory");
}
__device__ __forceinline__ void mbar_expect_tx(unsigned mbar, unsigned bytes) {
    asm volatile("mbarrier.arrive.expect_tx.shared.b64 _, [%0], %1;"
                 :: "r"(mbar), "r"(bytes) : "memory");
}
__device__ __forceinline__ void mbar_wait_parity(unsigned mbar, unsigned parity) {
    asm volatile(
        "{\n\t"
        ".reg .pred P;\n"
        "LW_%=:\n\t"
        "mbarrier.try_wait.parity.acquire.cta.shared::cta.b64 P, [%0], %1, 0x989680;\n\t"
        "@P bra LD_%=;\n\t"
        "bra LW_%=;\n"
        "LD_%=:\n\t"
        "}"
        :: "r"(mbar), "r"(parity) : "memory");
}
__device__ __forceinline__ unsigned elect1() {
    unsigned p;
    asm volatile("{\n\t.reg .pred p;\n\telect.sync _|p, 0xFFFFFFFF;\n\t"
                 "selp.b32 %0, 1, 0, p;\n\t}" : "=r"(p));
    return p;
}

// ---------- scratch (device globals: allocation-free rule) ----------
__device__ float g_xp[(size_t)BATCHN * S_LEN * HDIM];  // X@W_ih + b_hh, [b][s][h]
__device__ float g_h [(size_t)BATCHN * S_LEN * HDIM];  // hidden states,  [b][s][h]

// ============================================================================
// Kernel A: g_xp[M,512] = X[M,256] @ W_ih[256,512] + b_hh, M = 131072
// ============================================================================
__global__ void __launch_bounds__(256, 2) xproj_kernel(
    const float* __restrict__ X, const float* __restrict__ Wih,
    const float* __restrict__ bhh)
{
    __shared__ float As[128][17];
    __shared__ float Bs[16][128];
    const int tid = threadIdx.x;
    const int m0 = blockIdx.x * 128;
    const int n0 = blockIdx.y * 128;
    const int tx = tid & 15, ty = tid >> 4;

    ull acc[8][4];
#pragma unroll
    for (int i = 0; i < 8; i++)
#pragma unroll
        for (int j = 0; j < 4; j++) acc[i][j] = 0ull;

    for (int k0 = 0; k0 < IDIM; k0 += 16) {
#pragma unroll
        for (int i = 0; i < 2; i++) {
            int f4  = tid + i * 256;
            int row = f4 >> 2;
            int c4  = (f4 & 3) << 2;
            float4 v = *(const float4*)(X + (size_t)(m0 + row) * IDIM + k0 + c4);
            As[row][c4 + 0] = v.x; As[row][c4 + 1] = v.y;
            As[row][c4 + 2] = v.z; As[row][c4 + 3] = v.w;
        }
#pragma unroll
        for (int i = 0; i < 2; i++) {
            int f4  = tid + i * 256;
            int row = f4 >> 5;
            int c4  = (f4 & 31) << 2;
            *(float4*)&Bs[row][c4] =
                *(const float4*)(Wih + (size_t)(k0 + row) * HDIM + n0 + c4);
        }
        __syncthreads();
#pragma unroll
        for (int k = 0; k < 16; k++) {
            ulonglong2 bv0 = *(const ulonglong2*)&Bs[k][tx * 4];
            ulonglong2 bv1 = *(const ulonglong2*)&Bs[k][64 + tx * 4];
#pragma unroll
            for (int i = 0; i < 8; i++) {
                ull a2 = splat2(As[ty * 8 + i][k]);
                acc[i][0] = ffma2(a2, bv0.x, acc[i][0]);
                acc[i][1] = ffma2(a2, bv0.y, acc[i][1]);
                acc[i][2] = ffma2(a2, bv1.x, acc[i][2]);
                acc[i][3] = ffma2(a2, bv1.y, acc[i][3]);
            }
        }
        __syncthreads();
    }

#pragma unroll
    for (int i = 0; i < 8; i++) {
        float* dst = g_xp + (size_t)(m0 + ty * 8 + i) * HDIM + n0;
#pragma unroll
        for (int j = 0; j < 4; j++) {
            int n = (j < 2) ? (tx * 4 + j * 2) : (64 + tx * 4 + (j - 2) * 2);
            float2 v = upk2(acc[i][j]);
            v.x += bhh[n0 + n];
            v.y += bhh[n0 + n + 1];
            *(float2*)(dst + n) = v;
        }
    }
}

// empty launch to shift ncu's fixed profiled-launch slot onto rnn_kernel
__global__ void dummy_kernel() {}

// ============================================================================
// Kernel B: serial recurrence (R9 structure + K-PAIR PACKED inner loop).
// 16 clusters x 8 CTAs; 512 threads. Rank r owns W_hh cols [64r,64r+64),
// stored as K-PAIRS: Wp2[kp][j] = (W[2kp][c0+j], W[2kp+1][c0+j]) ull.
// h exchanged as natural k-pairs: hx block [kp32][b8] ull (2KB, same as R9).
//
// Warp w: k-chunk kc = w>>1 (source rank kc), column half jh = w&1;
// lane owns column j = jh*32 + l, all 8 batches. Per kp-iter:
//   1 LDS.64 (W pair, lane-distinct) + 4 broadcast LDS.128 (8 h-pairs)
//   + 8 FFMA2 (acc[b] even/odd-k halves) = 13 instr — NO splat MOVs.
// Reducer warp w (b=w), lane l -> cols (2l, 2l+1): folds even/odd halves,
// + xp, tanh, stores (h0,h1) as ONE STS.64 pair into own hx block.
// mbars / parity / syncthreads / push: identical to R9.
// ============================================================================
#define NT 512
// ull offsets: Wp2[256][64]=16384 | prt[16][8][32]=4096 | hx[2][8][256]=4096
#define U_PRT 16384
#define U_HX  20480
#define HX_BYTE 163840u               // U_HX * 8
#define MB_BYTE 196608u               // (U_HX + 4096) * 8
#define SMEMB_BYTES (196608 + 128)
#define BSTRIDE ((size_t)S_LEN * HDIM)
#define BLK_BYTES 2048u               // one source block (32 kp x 8 b x 8B)

__global__ void __launch_bounds__(NT, 1) __cluster_dims__(8, 1, 1)
rnn_kernel(const float* __restrict__ Whh)
{
    extern __shared__ float sm[];
    ull* Wp2 = (ull*)sm;               // [kp256][j64]
    ull* prt = Wp2 + U_PRT;            // [w16][b8][j32] (j within half)
    ull* hx  = Wp2 + U_HX;             // [slot2][src8][kp32][b8]

    const int tid  = threadIdx.x;
    const int rank = blockIdx.x & 7;
    const int g    = blockIdx.x >> 3;
    const int c0   = rank * 64;
    const unsigned smb    = s2u32(sm);
    const unsigned mb_loc = smb + MB_BYTE;   // mb[src][slot]: +(src*2+slot)*8

    if (tid == 0) {
#pragma unroll
        for (int i = 0; i < 16; i++) {
            mbar_init(mb_loc + i * 8, 1);
            mbar_expect_tx(mb_loc + i * 8, BLK_BYTES);
        }
    }

    // Build W k-pairs once (128KB): Wp2[kp][j] = (W[2kp][c0+j], W[2kp+1][c0+j])
    for (int i = tid; i < 256 * 64; i += NT) {
        int kp = i >> 6, j = i & 63;
        float lo = Whh[(size_t)(2 * kp)     * HDIM + c0 + j];
        float hi = Whh[(size_t)(2 * kp + 1) * HDIM + c0 + j];
        ((float2*)Wp2)[i] = make_float2(lo, hi);
    }
    // zero hx (h0 = 0), both slots
    for (int i = tid; i < 2 * 8 * 256; i += NT) hx[i] = 0ull;
    __syncthreads();
    asm volatile("barrier.cluster.arrive.aligned;" ::: "memory");
    asm volatile("barrier.cluster.wait.aligned;"   ::: "memory");

    const int w  = tid >> 5, l = tid & 31;
    const int kc = w >> 1;              // k-chunk / source rank
    const int jh = w & 1;               // column half

    // phase-1 pointers
    const ull* wsp = Wp2 + (size_t)(kc * 32) * 64 + jh * 32 + l;  // [kp*64]
    const ull* hxc = hx + kc * 256;     // + slot*2048 + kp*8

    // reducer mapping (warps 0-7): b = w, lane l -> cols (2l, 2l+1)
    const int half = l >> 4;            // which column half holds col 2l
    const int j0   = (2 * l) & 31;      // col index within half
    const float* xpp = g_xp + ((size_t)(g * 8 + w)) * BSTRIDE + c0 + 2 * l;
    float*       ghw = g_h  + ((size_t)(g * 8 + w)) * BSTRIDE + c0 + 2 * l;
    // own-block pair STS: hx[slot][rank][kp=l][b=w]
    ull* hxo = hx + rank * 256 + l * 8 + w;   // + slot*2048

    // bulk targets: peer r's hx[0][rank] block + peer r's mb[rank][0]
    unsigned peer_hx[8], peer_mb[8];
    {
        const unsigned hx0 = smb + HX_BYTE + (unsigned)rank * BLK_BYTES;
        const unsigned mb0 = mb_loc + (unsigned)(rank * 16);
#pragma unroll
        for (int r = 0; r < 8; r++) {
            peer_hx[r] = mapa_rank(hx0, (unsigned)r);
            peer_mb[r] = mapa_rank(mb0, (unsigned)r);
        }
    }
    const unsigned src_loc = smb + HX_BYTE + (unsigned)rank * BLK_BYTES;
    const unsigned mb_src  = mb_loc + (unsigned)(kc * 16);
    const bool self_src    = (kc == rank);
    const bool rearm_warp  = ((w & 1) == 0);

    for (int t = 0; t < S_LEN; t++) {
        const int wb = t & 1, rb = wb ^ 1;

        // xp prefetch (reducers), issued before the wait so it rides it
        ull xv = 0;
        if (w < 8) xv = *(const ull*)(xpp + (size_t)t * HDIM);

        // ---- per-source wait: only this warp's source block ----
        if (t > 0 && !self_src) {
            const unsigned mb = mb_src + (unsigned)(rb * 8);
            mbar_wait_parity(mb, (unsigned)(((t - 1) >> 1) & 1));
            if (rearm_warp && elect1()) mbar_expect_tx(mb, BLK_BYTES);
        }

        // ---- phase 1: k-pair packed, 1 col x 8 batches per lane, 32 kp ----
        const ull* hk = hxc + rb * 2048;
        ull a0 = 0, a1 = 0, a2 = 0, a3 = 0, a4 = 0, a5 = 0, a6 = 0, a7 = 0;
#pragma unroll 4
        for (int kp = 0; kp < 32; kp++) {
            ull wv = wsp[kp * 64];
            const ull* hb = hk + kp * 8;
            ulonglong2 h01 = *(const ulonglong2*)(hb + 0);
            ulonglong2 h23 = *(const ulonglong2*)(hb + 2);
            ulonglong2 h45 = *(const ulonglong2*)(hb + 4);
            ulonglong2 h67 = *(const ulonglong2*)(hb + 6);
            a0 = ffma2(wv, h01.x, a0);
            a1 = ffma2(wv, h01.y, a1);
            a2 = ffma2(wv, h23.x, a2);
            a3 = ffma2(wv, h23.y, a3);
            a4 = ffma2(wv, h45.x, a4);
            a5 = ffma2(wv, h45.y, a5);
            a6 = ffma2(wv, h67.x, a6);
            a7 = ffma2(wv, h67.y, a7);
        }
        {
            ull* pw = prt + w * 256 + l;
            pw[0 * 32] = a0; pw[1 * 32] = a1;
            pw[2 * 32] = a2; pw[3 * 32] = a3;
            pw[4 * 32] = a4; pw[5 * 32] = a5;
            pw[6 * 32] = a6; pw[7 * 32] = a7;
        }
        __syncthreads();

        // ---- phase 2 (warps 0-7): fold halves, reduce 8 chunks, tanh ----
        if (w < 8) {
            // partial rows: w' = 2*kcc + half; cols (j0, j0+1) as ulonglong2
            const ull* pb = prt + half * 256 + w * 32 + j0;
            ulonglong2 u0 = *(const ulonglong2*)(pb + 0 * 512);
            ulonglong2 u1 = *(const ulonglong2*)(pb + 1 * 512);
            ulonglong2 u2 = *(const ulonglong2*)(pb + 2 * 512);
            ulonglong2 u3 = *(const ulonglong2*)(pb + 3 * 512);
            ulonglong2 u4 = *(const ulonglong2*)(pb + 4 * 512);
            ulonglong2 u5 = *(const ulonglong2*)(pb + 5 * 512);
            ulonglong2 u6 = *(const ulonglong2*)(pb + 6 * 512);
            ulonglong2 u7 = *(const ulonglong2*)(pb + 7 * 512);
            ull se = add2(add2(add2(u0.x, u1.x), add2(u2.x, u3.x)),
                          add2(add2(u4.x, u5.x), add2(u6.x, u7.x)));
            ull so = add2(add2(add2(u0.y, u1.y), add2(u2.y, u3.y)),
                          add2(add2(u4.y, u5.y), add2(u6.y, u7.y)));
            float2 fe = upk2(se);
            float2 fo = upk2(so);
            float2 xf = upk2(xv);
            float h0 = tanhf(fe.x + fe.y + xf.x);   // col 2l
            float h1 = tanhf(fo.x + fo.y + xf.y);   // col 2l+1
            *(float2*)(ghw + (size_t)t * HDIM) = make_float2(h0, h1);
            if (t < S_LEN - 1)
                *(float2*)(hxo + wb * 2048) = make_float2(h0, h1);  // k-pair!
        }
        if (t == S_LEN - 1) break;   // nobody needs h(S)

        __syncthreads();   // own-block STS visible + prt reads done

        if (tid < 8 && tid != rank) {
            asm volatile("fence.proxy.async.shared::cta;" ::: "memory");
            bulk_s2c(peer_hx[tid] + (unsigned)wb * 16384u,
                     src_loc + (unsigned)wb * 16384u,
                     BLK_BYTES,
                     peer_mb[tid] + (unsigned)wb * 8);
        }
    }
}

// ============================================================================
// Kernel C: out[M,64] = g_h[M,512] @ W_ho[512,64] + b_ho, M = 131072
// ============================================================================
__global__ void __launch_bounds__(256) out_kernel(
    const float* __restrict__ Who, const float* __restrict__ bho,
    float* __restrict__ out)
{
    __shared__ float As[128][17];
    __shared__ float Bs[16][64];
    const int tid = threadIdx.x;
    const int m0 = blockIdx.x * 128;
    const int tx = tid & 15, ty = tid >> 4;

    ull acc[8][2];
#pragma unroll
    for (int i = 0; i < 8; i++) { acc[i][0] = 0ull; acc[i][1] = 0ull; }

    for (int k0 = 0; k0 < HDIM; k0 += 16) {
#pragma unroll
        for (int i = 0; i < 2; i++) {
            int f4  = tid + i * 256;
            int row = f4 >> 2;
            int c4  = (f4 & 3) << 2;
            float4 v = *(const float4*)(g_h + (size_t)(m0 + row) * HDIM + k0 + c4);
            As[row][c4 + 0] = v.x; As[row][c4 + 1] = v.y;
            As[row][c4 + 2] = v.z; As[row][c4 + 3] = v.w;
        }
        {
            int row = tid >> 4;
            int c4  = (tid & 15) << 2;
            *(float4*)&Bs[row][c4] =
                *(const float4*)(Who + (size_t)(k0 + row) * ODIM + c4);
        }
        __syncthreads();
#pragma unroll
        for (int k = 0; k < 16; k++) {
            ulonglong2 bv = *(const ulonglong2*)&Bs[k][tx * 4];
#pragma unroll
            for (int i = 0; i < 8; i++) {
                ull a2 = splat2(As[ty * 8 + i][k]);
                acc[i][0] = ffma2(a2, bv.x, acc[i][0]);
                acc[i][1] = ffma2(a2, bv.y, acc[i][1]);
            }
        }
        __syncthreads();
    }

    float bb0 = bho[tx * 4 + 0], bb1 = bho[tx * 4 + 1];
    float bb2 = bho[tx * 4 + 2], bb3 = bho[tx * 4 + 3];
#pragma unroll
    for (int i = 0; i < 8; i++) {
        float2 v0 = upk2(acc[i][0]); v0.x += bb0; v0.y += bb1;
        float2 v1 = upk2(acc[i][1]); v1.x += bb2; v1.y += bb3;
        float* dst = out + (size_t)(m0 + ty * 8 + i) * ODIM + tx * 4;
        *(float2*)(dst + 0) = v0;
        *(float2*)(dst + 2) = v1;
    }
}

// ============================================================================
extern "C" void kernel_launch(void* const* d_in, const int* in_sizes, int n_in,
                              void* d_out, int out_size)
{
    const float* X   = (const float*)d_in[0];   // [128,1024,256]
    const float* Whh = (const float*)d_in[1];   // [512,512]
    const float* Wih = (const float*)d_in[2];   // [256,512]
    const float* bhh = (const float*)d_in[3];   // [512]
    const float* Who = (const float*)d_in[4];   // [512,64]
    const float* bho = (const float*)d_in[5];   // [64]
    float* out = (float*)d_out;                 // [128,1024,64]

    cudaFuncSetAttribute(rnn_kernel,
                         cudaFuncAttributeMaxDynamicSharedMemorySize,
                         SMEMB_BYTES);

    xproj_kernel<<<dim3(1024, 4, 1), 256>>>(X, Wih, bhh);
    dummy_kernel<<<1, 32>>>();
    dummy_kernel<<<1, 32>>>();
    rnn_kernel<<<128, NT, SMEMB_BYTES>>>(Whh);
    out_kernel<<<1024, 256>>>(Who, bho, out);
}